// round 2
// baseline (speedup 1.0000x reference)
#include <cuda_runtime.h>
#include <math.h>

// ---------------------------------------------------------------------------
// AutoBoxGraphAttention: B=8, C=512, H=W=64, NH=8, HD=64
// Round 2: f32x2 packed FMA (FFMA2) in all GEMM inner loops; drop copy_x by
// two-source conv input (x | agg).
// ---------------------------------------------------------------------------

#define BATCH 8
#define HW 4096   // 64*64

typedef unsigned long long u64;

// ------------------------- device scratch buffers --------------------------
__device__ float g_wt_box1[4608 * 64];
__device__ float g_wt_edge1[36 * 64];
__device__ float g_wt_qkv[512 * 1536];
__device__ float g_wt_fus[9216 * 512];
__device__ float g_t1[BATCH * 64 * HW];      // box conv1 out (post-GELU)
__device__ float g_boxes[BATCH * 4 * HW];
__device__ float g_e1[BATCH * 64 * HW];      // edge conv1 out / GN in-place
__device__ float g_edge[BATCH * 8 * HW];
__device__ float g_qkv[BATCH * 1536 * HW];   // 192 MB
__device__ float g_S[BATCH * 8 * 64 * HW];   // 67 MB  S[b,h,i,w,W]
__device__ float g_agg[BATCH * 512 * HW];    // attention output (second conv source)
__device__ float g_y[BATCH * 512 * HW];      // fusion conv out
__device__ float g_bnmean[512];
__device__ float g_bnvar[512];

// ------------------------------ helpers ------------------------------------
__device__ __forceinline__ float gelu_exact(float v) {
    return 0.5f * v * (1.0f + erff(v * 0.70710678118654752f));
}
__device__ __forceinline__ float sigmoidf_(float v) {
    return 1.0f / (1.0f + expf(-v));
}
__device__ __forceinline__ float apply_act(float v, int act) {
    if (act == 1) return gelu_exact(v);
    if (act == 2) return sigmoidf_(v);
    return v;
}

// ---- packed f32x2 ops (Blackwell FFMA2, PTX-only) ----
__device__ __forceinline__ u64 dup2(float v) {
    u64 r; asm("mov.b64 %0, {%1, %1};" : "=l"(r) : "f"(v)); return r;
}
__device__ __forceinline__ u64 pack2(float lo, float hi) {
    u64 r; asm("mov.b64 %0, {%1, %2};" : "=l"(r) : "f"(lo), "f"(hi)); return r;
}
__device__ __forceinline__ void fma2(u64& d, u64 a, u64 b) {
    asm("fma.rn.f32x2 %0, %1, %2, %0;" : "+l"(d) : "l"(a), "l"(b));
}
__device__ __forceinline__ float2 unpack2(u64 p) {
    float lo, hi; asm("mov.b64 {%0, %1}, %2;" : "=f"(lo), "=f"(hi) : "l"(p));
    return make_float2(lo, hi);
}

// block reduce for 256 threads (8 warps); sh must hold >= 8 floats
__device__ __forceinline__ float block_reduce_sum_256(float v, float* sh) {
    #pragma unroll
    for (int o = 16; o; o >>= 1) v += __shfl_xor_sync(0xffffffffu, v, o);
    int w = threadIdx.x >> 5;
    if ((threadIdx.x & 31) == 0) sh[w] = v;
    __syncthreads();
    float r = 0.0f;
    if (threadIdx.x < 8) {
        r = sh[threadIdx.x];
        #pragma unroll
        for (int o = 4; o; o >>= 1) r += __shfl_xor_sync(0xffu, r, o);
    }
    if (threadIdx.x == 0) sh[0] = r;
    __syncthreads();
    float out = sh[0];
    __syncthreads();
    return out;
}

// --------------------------- weight transpose -------------------------------
// w[Cout][K] -> wt[K][Cout]
__global__ void transpose_w(const float* __restrict__ w, float* __restrict__ wt,
                            int Cout, int K) {
    __shared__ float tile[32][33];
    int k = blockIdx.x * 32 + threadIdx.x;
    int co = blockIdx.y * 32 + threadIdx.y;
    if (co < Cout && k < K) tile[threadIdx.y][threadIdx.x] = w[co * K + k];
    __syncthreads();
    int k2 = blockIdx.x * 32 + threadIdx.y;
    int co2 = blockIdx.y * 32 + threadIdx.x;
    if (k2 < K && co2 < Cout) wt[k2 * Cout + co2] = tile[threadIdx.x][threadIdx.y];
}

// ------------------ implicit-GEMM conv (NCHW), FFMA2 inner -------------------
// Input channels ci < Csplit read from in0, else from in1 (channel ci-Csplit).
// A tile stored DUPLICATED in shared so both FFMA2 operands come from LDS.128.
template<int BM, int BN, int BK, int TM, int TN, int R>
__global__ void __launch_bounds__(256)
conv_f2(const float* __restrict__ in0, const float* __restrict__ in1, int Csplit,
        const float* __restrict__ wt, const float* __restrict__ bias,
        float* __restrict__ out, int Cin, int Cout, int act) {
    constexpr int TPB = (BM / TM) * (BN / TN);
    const int tid = threadIdx.x;
    const int Ktot = Cin * R * R;
    const int m0 = blockIdx.y * BM;
    const int n0 = blockIdx.x * BN;
    const int b = n0 >> 12;
    const int p0 = n0 & 4095;
    const int y0 = p0 >> 6;
    const int Cin1 = Cin - Csplit;

    __shared__ float As2[BK][2 * BM];
    __shared__ float Bs[BK][BN];

    u64 acc2[TM][TN / 2];
    #pragma unroll
    for (int i = 0; i < TM; i++)
        #pragma unroll
        for (int j = 0; j < TN / 2; j++) acc2[i][j] = 0ull;

    const int tn = tid % (BN / TN);
    const int tm = tid / (BN / TN);

    for (int k0 = 0; k0 < Ktot; k0 += BK) {
        // A tile: wt[K][Cout], duplicated per element
        #pragma unroll
        for (int it = 0; it < (BM * BK) / TPB; it++) {
            int i = tid + it * TPB;
            int m = i % BM, k = i / BM;
            int kk = k0 + k;
            float v = (kk < Ktot) ? wt[kk * Cout + m0 + m] : 0.0f;
            As2[k][2 * m] = v;
            As2[k][2 * m + 1] = v;
        }
        // B tile: gathered im2col, coalesced over n
        #pragma unroll
        for (int it = 0; it < (BN * BK) / TPB; it++) {
            int i = tid + it * TPB;
            int n = i % BN, k = i / BN;
            int kk = k0 + k;
            float v = 0.0f;
            if (kk < Ktot) {
                int ci, sy, sx;
                if (R == 3) {
                    ci = kk / 9;
                    int r = kk - ci * 9;
                    int ky = r / 3, kx = r - ky * 3;
                    sy = y0 + (n >> 6) + ky - 1;
                    sx = (n & 63) + kx - 1;
                } else {
                    ci = kk;
                    sy = y0 + (n >> 6);
                    sx = n & 63;
                }
                if ((unsigned)sy < 64u && (unsigned)sx < 64u) {
                    const float* base = (ci < Csplit)
                        ? in0 + (((size_t)(b * Csplit + ci)) << 12)
                        : in1 + (((size_t)(b * Cin1 + (ci - Csplit))) << 12);
                    v = base[(sy << 6) + sx];
                }
            }
            Bs[k][n] = v;
        }
        __syncthreads();
        #pragma unroll
        for (int k = 0; k < BK; k++) {
            u64 a2[TM], b2[TN / 2];
            const ulonglong2* ap = (const ulonglong2*)&As2[k][tm * TM * 2];
            #pragma unroll
            for (int ii = 0; ii < TM / 2; ii++) {
                ulonglong2 t = ap[ii];
                a2[2 * ii] = t.x; a2[2 * ii + 1] = t.y;
            }
            const ulonglong2* bp = (const ulonglong2*)&Bs[k][tn * TN];
            #pragma unroll
            for (int jj = 0; jj < TN / 4; jj++) {
                ulonglong2 t = bp[jj];
                b2[2 * jj] = t.x; b2[2 * jj + 1] = t.y;
            }
            #pragma unroll
            for (int i = 0; i < TM; i++)
                #pragma unroll
                for (int j = 0; j < TN / 2; j++)
                    fma2(acc2[i][j], a2[i], b2[j]);
        }
        __syncthreads();
    }

    #pragma unroll
    for (int i = 0; i < TM; i++) {
        int co = m0 + tm * TM + i;
        float bs = bias[co];
        float* orow = out + (((size_t)(b * Cout + co)) << 12) + p0 + tn * TN;
        #pragma unroll
        for (int j = 0; j < TN / 2; j++) {
            float2 v = unpack2(acc2[i][j]);
            float2 o;
            o.x = apply_act(v.x + bs, act);
            o.y = apply_act(v.y + bs, act);
            *(float2*)&orow[2 * j] = o;
        }
    }
}

// ------------------------ small 1x1 conv (Cout tiny) -------------------------
template<int COUT, int CIN>
__global__ void conv1x1_small(const float* __restrict__ in, const float* __restrict__ w,
                              const float* __restrict__ bias, float* __restrict__ out,
                              int act) {
    __shared__ float ws[COUT * CIN];
    for (int i = threadIdx.x; i < COUT * CIN; i += blockDim.x) ws[i] = w[i];
    __syncthreads();
    int idx = blockIdx.x * blockDim.x + threadIdx.x; // over B*HW
    if (idx >= BATCH * HW) return;
    int b = idx >> 12, p = idx & 4095;
    float acc[COUT];
    #pragma unroll
    for (int co = 0; co < COUT; co++) acc[co] = bias[co];
    for (int ci = 0; ci < CIN; ci++) {
        float v = in[((b * CIN + ci) << 12) + p];
        #pragma unroll
        for (int co = 0; co < COUT; co++) acc[co] += ws[co * CIN + ci] * v;
    }
    #pragma unroll
    for (int co = 0; co < COUT; co++)
        out[((b * COUT + co) << 12) + p] = apply_act(acc[co], act);
}

// ---------------------- GroupNorm(8 groups of 8ch) + GELU -------------------
__global__ void groupnorm_gelu(float* __restrict__ e, const float* __restrict__ g,
                               const float* __restrict__ bta) {
    __shared__ float sh[8];
    int b = blockIdx.x >> 3, grp = blockIdx.x & 7;
    const int base = (b * 64 + grp * 8) << 12; // 8 channels * 4096
    float s = 0.0f, s2 = 0.0f;
    for (int i = threadIdx.x; i < 8 * HW; i += blockDim.x) {
        float v = e[base + i];
        s += v; s2 += v * v;
    }
    s = block_reduce_sum_256(s, sh);
    s2 = block_reduce_sum_256(s2, sh);
    float mean = s * (1.0f / 32768.0f);
    float var = s2 * (1.0f / 32768.0f) - mean * mean;
    float rstd = rsqrtf(var + 1e-5f);
    for (int i = threadIdx.x; i < 8 * HW; i += blockDim.x) {
        int ch = grp * 8 + (i >> 12);
        float v = (e[base + i] - mean) * rstd * g[ch] + bta[ch];
        e[base + i] = gelu_exact(v);
    }
}

// ---------------- attention: S = Q^T K / 8 + edge (FFMA2 inner) -------------
__global__ void __launch_bounds__(256) qk_kernel(const float* __restrict__ qkv,
                                                 const float* __restrict__ edge,
                                                 float* __restrict__ S) {
    int blk = blockIdx.x;           // b*512 + h*64 + i
    int b = blk >> 9;
    int hi = blk & 511;
    const float* Q = qkv + (((size_t)(b * 1536 + hi)) << 12);
    const float* K = qkv + (((size_t)(b * 1536 + 512 + hi)) << 12);
    const float* E = edge + ((size_t)blk << 6);

    __shared__ float Qs[64 * 64];
    __shared__ float Ks[64 * 64];
    __shared__ float Es[64];
    int tid = threadIdx.x;
    #pragma unroll
    for (int it = 0; it < 4; it++) {
        int i = tid + it * 256;
        ((float4*)Qs)[i] = ((const float4*)Q)[i];
        ((float4*)Ks)[i] = ((const float4*)K)[i];
    }
    if (tid < 64) Es[tid] = E[tid];
    __syncthreads();

    int tW = tid & 15, tw = tid >> 4;
    u64 acc2[4][2];
    #pragma unroll
    for (int r = 0; r < 4; r++) { acc2[r][0] = 0ull; acc2[r][1] = 0ull; }

    #pragma unroll 4
    for (int d = 0; d < 64; d++) {
        float4 qv = *(const float4*)&Qs[d * 64 + tw * 4];
        float4 kv = *(const float4*)&Ks[d * 64 + tW * 4];
        u64 b0 = pack2(kv.x, kv.y), b1 = pack2(kv.z, kv.w);
        u64 aq[4] = {dup2(qv.x), dup2(qv.y), dup2(qv.z), dup2(qv.w)};
        #pragma unroll
        for (int r = 0; r < 4; r++) {
            fma2(acc2[r][0], aq[r], b0);
            fma2(acc2[r][1], aq[r], b1);
        }
    }
    float* So = S + ((size_t)blk << 12);
    #pragma unroll
    for (int r = 0; r < 4; r++) {
        int w = tw * 4 + r;
        float e = Es[w];
        #pragma unroll
        for (int j = 0; j < 2; j++) {
            float2 v = unpack2(acc2[r][j]);
            float2 o;
            o.x = v.x * 0.125f + e;
            o.y = v.y * 0.125f + e;
            *(float2*)&So[w * 64 + tW * 4 + 2 * j] = o;
        }
    }
}

// ------------------- softmax over i (stride 4096 within bh) -----------------
__global__ void __launch_bounds__(256) softmax_i(float* __restrict__ S) {
    int col = blockIdx.x * blockDim.x + threadIdx.x; // over 8*8*4096
    if (col >= 64 * HW) return;
    int bh = col >> 12, p = col & 4095;
    float* base = S + ((size_t)bh << 18) + p; // bh * 64 * 4096
    float vals[64];
    float mx = -3.0e38f;
    #pragma unroll
    for (int i = 0; i < 64; i++) {
        vals[i] = base[i << 12];
        mx = fmaxf(mx, vals[i]);
    }
    float sum = 0.0f;
    #pragma unroll
    for (int i = 0; i < 64; i++) {
        vals[i] = expf(vals[i] - mx);
        sum += vals[i];
    }
    float inv = 1.0f / sum;
    #pragma unroll
    for (int i = 0; i < 64; i++) base[i << 12] = vals[i] * inv;
}

// ---------------- agg = V A^T, write into g_agg -----------------------------
__global__ void __launch_bounds__(256) av_kernel(const float* __restrict__ S,
                                                 const float* __restrict__ qkv,
                                                 float* __restrict__ agg) {
    int blk = blockIdx.x; // b*512 + hi
    int b = blk >> 9;
    int hi = blk & 511;
    const float* A = S + ((size_t)blk << 12);                       // A[w][W]
    const float* V = qkv + (((size_t)(b * 1536 + 1024 + hi)) << 12); // V[d][W]

    __shared__ float As_[64][65];
    __shared__ float Vs[64][65];
    int tid = threadIdx.x;
    #pragma unroll
    for (int it = 0; it < 16; it++) {
        int i = tid + it * 256;
        int r = i >> 6, c = i & 63;
        As_[r][c] = A[i];
        Vs[r][c] = V[i];
    }
    __syncthreads();

    int tw = tid & 15, td = tid >> 4;
    float acc[4][4]; // acc[d][w]
    #pragma unroll
    for (int r = 0; r < 4; r++)
        #pragma unroll
        for (int c = 0; c < 4; c++) acc[r][c] = 0.0f;

    #pragma unroll 4
    for (int W = 0; W < 64; W++) {
        float v[4], a[4];
        #pragma unroll
        for (int r = 0; r < 4; r++) v[r] = Vs[td * 4 + r][W];
        #pragma unroll
        for (int c = 0; c < 4; c++) a[c] = As_[tw * 4 + c][W];
        #pragma unroll
        for (int r = 0; r < 4; r++)
            #pragma unroll
            for (int c = 0; c < 4; c++) acc[r][c] += v[r] * a[c];
    }
    float* out = agg + (((size_t)(b * 512 + hi)) << 12);
    #pragma unroll
    for (int r = 0; r < 4; r++)
        #pragma unroll
        for (int c = 0; c < 4; c++)
            out[(td * 4 + r) * 64 + tw * 4 + c] = acc[r][c];
}

// ------------------------- BatchNorm stats + SiLU ---------------------------
__global__ void bn_stats(const float* __restrict__ y, float* __restrict__ mean,
                         float* __restrict__ var) {
    __shared__ float sh[8];
    int c = blockIdx.x;
    float s = 0.0f, s2 = 0.0f;
    for (int i = threadIdx.x; i < BATCH * HW; i += blockDim.x) {
        int b = i >> 12, p = i & 4095;
        float v = y[(((size_t)(b * 512 + c)) << 12) + p];
        s += v; s2 += v * v;
    }
    s = block_reduce_sum_256(s, sh);
    s2 = block_reduce_sum_256(s2, sh);
    if (threadIdx.x == 0) {
        float m = s * (1.0f / 32768.0f);
        mean[c] = m;
        var[c] = s2 * (1.0f / 32768.0f) - m * m;
    }
}

__global__ void bn_silu(const float* __restrict__ y, const float* __restrict__ mean,
                        const float* __restrict__ var, const float* __restrict__ g,
                        const float* __restrict__ bta, float* __restrict__ out) {
    int idx = blockIdx.x * blockDim.x + threadIdx.x; // over B*512*HW
    int c = (idx >> 12) & 511;
    float v = (y[idx] - mean[c]) * rsqrtf(var[c] + 1e-5f) * g[c] + bta[c];
    out[idx] = v * sigmoidf_(v);
}

// ------------------------------- launcher -----------------------------------
static float* sym_addr(const void* symbol) {
    void* p = nullptr;
    cudaGetSymbolAddress(&p, symbol);
    return (float*)p;
}

extern "C" void kernel_launch(void* const* d_in, const int* in_sizes, int n_in,
                              void* d_out, int out_size) {
    const float* x       = (const float*)d_in[0];
    const float* box_w1  = (const float*)d_in[1];
    const float* box_b1  = (const float*)d_in[2];
    const float* box_w2  = (const float*)d_in[3];
    const float* box_b2  = (const float*)d_in[4];
    const float* edge_w1 = (const float*)d_in[5];
    const float* edge_b1 = (const float*)d_in[6];
    const float* gn_g    = (const float*)d_in[7];
    const float* gn_b    = (const float*)d_in[8];
    const float* edge_w2 = (const float*)d_in[9];
    const float* edge_b2 = (const float*)d_in[10];
    const float* qkv_w   = (const float*)d_in[11];
    const float* qkv_b   = (const float*)d_in[12];
    const float* fus_w   = (const float*)d_in[13];
    const float* fus_b   = (const float*)d_in[14];
    const float* bn_g    = (const float*)d_in[15];
    const float* bn_b    = (const float*)d_in[16];
    float* out = (float*)d_out;

    float* wt_box1  = sym_addr(g_wt_box1);
    float* wt_edge1 = sym_addr(g_wt_edge1);
    float* wt_qkv   = sym_addr(g_wt_qkv);
    float* wt_fus   = sym_addr(g_wt_fus);
    float* t1       = sym_addr(g_t1);
    float* boxes    = sym_addr(g_boxes);
    float* e1       = sym_addr(g_e1);
    float* edge     = sym_addr(g_edge);
    float* qkvbuf   = sym_addr(g_qkv);
    float* Sbuf     = sym_addr(g_S);
    float* aggbuf   = sym_addr(g_agg);
    float* ybuf     = sym_addr(g_y);
    float* bnmean   = sym_addr(g_bnmean);
    float* bnvar    = sym_addr(g_bnvar);

    dim3 tb(32, 32);
    transpose_w<<<dim3(144, 2), tb>>>(box_w1, wt_box1, 64, 4608);
    transpose_w<<<dim3(2, 2), tb>>>(edge_w1, wt_edge1, 64, 36);
    transpose_w<<<dim3(16, 48), tb>>>(qkv_w, wt_qkv, 1536, 512);
    transpose_w<<<dim3(288, 16), tb>>>(fus_w, wt_fus, 512, 9216);

    // box_net
    conv_f2<64, 128, 16, 4, 8, 3><<<dim3(256, 1), 256>>>(
        x, x, 512, wt_box1, box_b1, t1, 512, 64, /*gelu*/1);
    conv1x1_small<4, 64><<<128, 256>>>(t1, box_w2, box_b2, boxes, /*sigmoid*/2);

    // edge_net
    conv_f2<64, 128, 16, 4, 8, 3><<<dim3(256, 1), 256>>>(
        boxes, boxes, 4, wt_edge1, edge_b1, e1, 4, 64, /*none*/0);
    groupnorm_gelu<<<64, 256>>>(e1, gn_g, gn_b);
    conv1x1_small<8, 64><<<128, 256>>>(e1, edge_w2, edge_b2, edge, /*none*/0);

    // qkv 1x1 conv
    conv_f2<128, 128, 16, 8, 8, 1><<<dim3(256, 12), 256>>>(
        x, x, 512, wt_qkv, qkv_b, qkvbuf, 512, 1536, 0);

    // attention
    qk_kernel<<<4096, 256>>>(qkvbuf, edge, Sbuf);
    softmax_i<<<1024, 256>>>(Sbuf);
    av_kernel<<<4096, 256>>>(Sbuf, qkvbuf, aggbuf);

    // fusion conv (two-source input: x | agg) + BN + SiLU
    conv_f2<128, 128, 16, 8, 8, 3><<<dim3(256, 4), 256>>>(
        x, aggbuf, 512, wt_fus, fus_b, ybuf, 1024, 512, 0);
    bn_stats<<<512, 256>>>(ybuf, bnmean, bnvar);
    bn_silu<<<65536, 256>>>(ybuf, bnmean, bnvar, bn_g, bn_b, out);
}

// round 3
// speedup vs baseline: 1.2849x; 1.2849x over previous
#include <cuda_runtime.h>
#include <math.h>
#include <stdint.h>

// ---------------------------------------------------------------------------
// AutoBoxGraphAttention: B=8, C=512, H=W=64, NH=8, HD=64
// Round 3: all convs as implicit-GEMM on tensor cores (mma.sync tf32),
// fragment-native shared layouts. Attention stays fp32 FFMA (tiny).
// ---------------------------------------------------------------------------

#define BATCH 8
#define HW 4096   // 64*64

// ------------------------- device scratch buffers --------------------------
__device__ float g_wt_box1[4608 * 64];
__device__ float g_wt_edge1[64 * 64];     // padded (36 used)
__device__ float g_wt_qkv[512 * 1536];
__device__ float g_wt_fus[9216 * 512];
__device__ float g_t1[BATCH * 64 * HW];
__device__ float g_boxes[BATCH * 4 * HW];
__device__ float g_e1[BATCH * 64 * HW];
__device__ float g_edge[BATCH * 8 * HW];
__device__ float g_qkv[BATCH * 1536 * HW];   // 192 MB
__device__ float g_S[BATCH * 8 * 64 * HW];   // 67 MB  S[b,h,i,w,W]
__device__ float g_agg[BATCH * 512 * HW];
__device__ float g_y[BATCH * 512 * HW];
__device__ float g_bnmean[512];
__device__ float g_bnvar[512];

// ------------------------------ helpers ------------------------------------
__device__ __forceinline__ float gelu_exact(float v) {
    return 0.5f * v * (1.0f + erff(v * 0.70710678118654752f));
}
__device__ __forceinline__ float sigmoidf_(float v) {
    return 1.0f / (1.0f + expf(-v));
}
__device__ __forceinline__ float apply_act(float v, int act) {
    if (act == 1) return gelu_exact(v);
    if (act == 2) return sigmoidf_(v);
    return v;
}
__device__ __forceinline__ uint32_t f2tf32(float v) {
    uint32_t u;
    asm("cvt.rna.tf32.f32 %0, %1;" : "=r"(u) : "f"(v));
    return u;
}
__device__ __forceinline__ void mma_tf32(float c[4], const uint32_t a[4],
                                         const uint32_t b[2]) {
    asm volatile(
        "mma.sync.aligned.m16n8k8.row.col.f32.tf32.tf32.f32 "
        "{%0,%1,%2,%3}, {%4,%5,%6,%7}, {%8,%9}, {%0,%1,%2,%3};"
        : "+f"(c[0]), "+f"(c[1]), "+f"(c[2]), "+f"(c[3])
        : "r"(a[0]), "r"(a[1]), "r"(a[2]), "r"(a[3]), "r"(b[0]), "r"(b[1]));
}

// block reduce for 256 threads (8 warps); sh must hold >= 8 floats
__device__ __forceinline__ float block_reduce_sum_256(float v, float* sh) {
    #pragma unroll
    for (int o = 16; o; o >>= 1) v += __shfl_xor_sync(0xffffffffu, v, o);
    int w = threadIdx.x >> 5;
    if ((threadIdx.x & 31) == 0) sh[w] = v;
    __syncthreads();
    float r = 0.0f;
    if (threadIdx.x < 8) {
        r = sh[threadIdx.x];
        #pragma unroll
        for (int o = 4; o; o >>= 1) r += __shfl_xor_sync(0xffu, r, o);
    }
    if (threadIdx.x == 0) sh[0] = r;
    __syncthreads();
    float out = sh[0];
    __syncthreads();
    return out;
}

// --------------------------- weight transpose -------------------------------
// w[Cout][K] -> wt[K][Cout]
__global__ void transpose_w(const float* __restrict__ w, float* __restrict__ wt,
                            int Cout, int K) {
    __shared__ float tile[32][33];
    int k = blockIdx.x * 32 + threadIdx.x;
    int co = blockIdx.y * 32 + threadIdx.y;
    if (co < Cout && k < K) tile[threadIdx.y][threadIdx.x] = w[co * K + k];
    __syncthreads();
    int k2 = blockIdx.x * 32 + threadIdx.y;
    int co2 = blockIdx.y * 32 + threadIdx.x;
    if (k2 < K && co2 < Cout) wt[k2 * Cout + co2] = tile[threadIdx.x][threadIdx.y];
}

// ------------------ implicit-GEMM conv on tensor cores (tf32) ---------------
// y[b, m0+m, p] = act(bias + sum_k wt[k][m0+m] * im2col[k][n]),  n = b*4096+p.
// Shared tiles stored in mma-fragment order:
//   A: per (m-tile 16, k-step 8): lane owns 4 contiguous tf32 (a0..a3)
//   B: per (n-tile 8,  k-step 8): lane owns 2 contiguous tf32 (b0,b1)
// Input channels ci < Csplit read from in0, else in1 (channel ci-Csplit).
template<int BM, int BN, int WM, int WN, int R>
__global__ void __launch_bounds__(256)
conv_mma(const float* __restrict__ in0, const float* __restrict__ in1, int Csplit,
         const float* __restrict__ wt, const float* __restrict__ bias,
         float* __restrict__ out, int Cin, int Cout, int act) {
    constexpr int BK = 16;
    constexpr int WARPS_N = BN / WN;
    constexpr int MT = WM / 16;   // m-tiles per warp
    constexpr int NT = WN / 8;    // n-tiles per warp

    const int tid = threadIdx.x;
    const int lane = tid & 31;
    const int w = tid >> 5;
    const int wm = w / WARPS_N;
    const int wn = w % WARPS_N;

    const int Ktot = Cin * R * R;
    const int m0 = blockIdx.y * BM;
    const int n0 = blockIdx.x * BN;
    const int b = n0 >> 12;
    const int p0 = n0 & 4095;
    const int y0 = p0 >> 6;
    const int Cin1 = Cin - Csplit;

    __shared__ uint32_t As[BM * BK];   // fragment-ordered
    __shared__ uint32_t Bs[BN * BK];   // fragment-ordered

    float c[MT][NT][4];
    #pragma unroll
    for (int i = 0; i < MT; i++)
        #pragma unroll
        for (int j = 0; j < NT; j++)
            #pragma unroll
            for (int q = 0; q < 4; q++) c[i][j][q] = 0.0f;

    for (int k0 = 0; k0 < Ktot; k0 += BK) {
        // ---- A fill: coalesced read over m, scatter to fragment slots ----
        #pragma unroll
        for (int it = 0; it < (BM * BK) / 256; it++) {
            int i = tid + it * 256;
            int m = i % BM, k = i / BM;
            int kk = k0 + k;
            float v = (kk < Ktot) ? wt[kk * Cout + m0 + m] : 0.0f;
            int mt = m >> 4, r = m & 15;
            int g = r & 7, t = k & 3;
            int jb = ((r >> 3) & 1) | (((k >> 2) & 1) << 1);
            int ks = k >> 3;
            As[(((mt * (BK / 8) + ks) * 32) + g * 4 + t) * 4 + jb] = f2tf32(v);
        }
        // ---- B fill: im2col gather (coalesced over n), scatter ----
        #pragma unroll
        for (int it = 0; it < (BN * BK) / 256; it++) {
            int i = tid + it * 256;
            int n = i % BN, k = i / BN;
            int kk = k0 + k;
            float v = 0.0f;
            if (kk < Ktot) {
                int ci, sy, sx;
                if (R == 3) {
                    ci = kk / 9;
                    int rr = kk - ci * 9;
                    int ky = rr / 3, kx = rr - ky * 3;
                    sy = y0 + (n >> 6) + ky - 1;
                    sx = (n & 63) + kx - 1;
                } else {
                    ci = kk;
                    sy = y0 + (n >> 6);
                    sx = n & 63;
                }
                if ((unsigned)sy < 64u && (unsigned)sx < 64u) {
                    const float* base = (ci < Csplit)
                        ? in0 + (((size_t)(b * Csplit + ci)) << 12)
                        : in1 + (((size_t)(b * Cin1 + (ci - Csplit))) << 12);
                    v = base[(sy << 6) + sx];
                }
            }
            int nt = n >> 3, g = n & 7;
            int t = k & 3, j = (k >> 2) & 1;
            int ks = k >> 3;
            Bs[(((nt * (BK / 8) + ks) * 32) + g * 4 + t) * 2 + j] = f2tf32(v);
        }
        __syncthreads();

        #pragma unroll
        for (int ks = 0; ks < BK / 8; ks++) {
            uint32_t af[MT][4];
            uint32_t bf[NT][2];
            #pragma unroll
            for (int mt = 0; mt < MT; mt++) {
                uint4 t4 = ((const uint4*)As)[((wm * MT + mt) * (BK / 8) + ks) * 32 + lane];
                af[mt][0] = t4.x; af[mt][1] = t4.y; af[mt][2] = t4.z; af[mt][3] = t4.w;
            }
            #pragma unroll
            for (int nt = 0; nt < NT; nt++) {
                uint2 t2 = ((const uint2*)Bs)[((wn * NT + nt) * (BK / 8) + ks) * 32 + lane];
                bf[nt][0] = t2.x; bf[nt][1] = t2.y;
            }
            #pragma unroll
            for (int mt = 0; mt < MT; mt++)
                #pragma unroll
                for (int nt = 0; nt < NT; nt++)
                    mma_tf32(c[mt][nt], af[mt], bf[nt]);
        }
        __syncthreads();
    }

    // ---- epilogue ----
    const int g = lane >> 2, t = lane & 3;
    #pragma unroll
    for (int mt = 0; mt < MT; mt++) {
        int row0 = m0 + wm * WM + mt * 16 + g;   // +0 and +8
        float bs0 = bias[row0];
        float bs1 = bias[row0 + 8];
        #pragma unroll
        for (int nt = 0; nt < NT; nt++) {
            int nl = wn * WN + nt * 8 + t * 2;
            int p = p0 + nl;
            float2 o0, o1;
            o0.x = apply_act(c[mt][nt][0] + bs0, act);
            o0.y = apply_act(c[mt][nt][1] + bs0, act);
            o1.x = apply_act(c[mt][nt][2] + bs1, act);
            o1.y = apply_act(c[mt][nt][3] + bs1, act);
            *(float2*)&out[(((size_t)(b * Cout + row0)) << 12) + p] = o0;
            *(float2*)&out[(((size_t)(b * Cout + row0 + 8)) << 12) + p] = o1;
        }
    }
}

// ------------------------ small 1x1 conv (Cout tiny) -------------------------
template<int COUT, int CIN>
__global__ void conv1x1_small(const float* __restrict__ in, const float* __restrict__ w,
                              const float* __restrict__ bias, float* __restrict__ out,
                              int act) {
    __shared__ float ws[COUT * CIN];
    for (int i = threadIdx.x; i < COUT * CIN; i += blockDim.x) ws[i] = w[i];
    __syncthreads();
    int idx = blockIdx.x * blockDim.x + threadIdx.x; // over B*HW
    if (idx >= BATCH * HW) return;
    int b = idx >> 12, p = idx & 4095;
    float acc[COUT];
    #pragma unroll
    for (int co = 0; co < COUT; co++) acc[co] = bias[co];
    for (int ci = 0; ci < CIN; ci++) {
        float v = in[((b * CIN + ci) << 12) + p];
        #pragma unroll
        for (int co = 0; co < COUT; co++) acc[co] += ws[co * CIN + ci] * v;
    }
    #pragma unroll
    for (int co = 0; co < COUT; co++)
        out[((b * COUT + co) << 12) + p] = apply_act(acc[co], act);
}

// ---------------------- GroupNorm(8 groups of 8ch) + GELU -------------------
__global__ void groupnorm_gelu(float* __restrict__ e, const float* __restrict__ g,
                               const float* __restrict__ bta) {
    __shared__ float sh[8];
    int b = blockIdx.x >> 3, grp = blockIdx.x & 7;
    const int base = (b * 64 + grp * 8) << 12;
    float s = 0.0f, s2 = 0.0f;
    for (int i = threadIdx.x; i < 8 * HW; i += blockDim.x) {
        float v = e[base + i];
        s += v; s2 += v * v;
    }
    s = block_reduce_sum_256(s, sh);
    s2 = block_reduce_sum_256(s2, sh);
    float mean = s * (1.0f / 32768.0f);
    float var = s2 * (1.0f / 32768.0f) - mean * mean;
    float rstd = rsqrtf(var + 1e-5f);
    for (int i = threadIdx.x; i < 8 * HW; i += blockDim.x) {
        int ch = grp * 8 + (i >> 12);
        float v = (e[base + i] - mean) * rstd * g[ch] + bta[ch];
        e[base + i] = gelu_exact(v);
    }
}

// ---------------------- attention: S = Q^T K / 8 + edge ---------------------
__global__ void __launch_bounds__(256) qk_kernel(const float* __restrict__ qkv,
                                                 const float* __restrict__ edge,
                                                 float* __restrict__ S) {
    int blk = blockIdx.x;           // b*512 + h*64 + i
    int b = blk >> 9;
    int hi = blk & 511;
    const float* Q = qkv + (((size_t)(b * 1536 + hi)) << 12);
    const float* K = qkv + (((size_t)(b * 1536 + 512 + hi)) << 12);
    const float* E = edge + ((size_t)blk << 6);

    __shared__ float Qs[64 * 64];
    __shared__ float Ks[64 * 64];
    __shared__ float Es[64];
    int tid = threadIdx.x;
    #pragma unroll
    for (int it = 0; it < 4; it++) {
        int i = tid + it * 256;
        ((float4*)Qs)[i] = ((const float4*)Q)[i];
        ((float4*)Ks)[i] = ((const float4*)K)[i];
    }
    if (tid < 64) Es[tid] = E[tid];
    __syncthreads();

    int tW = tid & 15, tw = tid >> 4;
    float acc[4][4];
    #pragma unroll
    for (int r = 0; r < 4; r++)
        #pragma unroll
        for (int c = 0; c < 4; c++) acc[r][c] = 0.0f;

    #pragma unroll 4
    for (int d = 0; d < 64; d++) {
        float4 qv = *(const float4*)&Qs[d * 64 + tw * 4];
        float4 kv = *(const float4*)&Ks[d * 64 + tW * 4];
        float qa[4] = {qv.x, qv.y, qv.z, qv.w};
        float ka[4] = {kv.x, kv.y, kv.z, kv.w};
        #pragma unroll
        for (int r = 0; r < 4; r++)
            #pragma unroll
            for (int c = 0; c < 4; c++) acc[r][c] += qa[r] * ka[c];
    }
    float* So = S + ((size_t)blk << 12);
    #pragma unroll
    for (int r = 0; r < 4; r++) {
        int ww = tw * 4 + r;
        float e = Es[ww];
        #pragma unroll
        for (int c = 0; c < 4; c++)
            So[ww * 64 + tW * 4 + c] = acc[r][c] * 0.125f + e;
    }
}

// ------------------- softmax over i (stride 4096 within bh) -----------------
__global__ void __launch_bounds__(256) softmax_i(float* __restrict__ S) {
    int col = blockIdx.x * blockDim.x + threadIdx.x;
    if (col >= 64 * HW) return;
    int bh = col >> 12, p = col & 4095;
    float* base = S + ((size_t)bh << 18) + p;
    float vals[64];
    float mx = -3.0e38f;
    #pragma unroll
    for (int i = 0; i < 64; i++) {
        vals[i] = base[i << 12];
        mx = fmaxf(mx, vals[i]);
    }
    float sum = 0.0f;
    #pragma unroll
    for (int i = 0; i < 64; i++) {
        vals[i] = expf(vals[i] - mx);
        sum += vals[i];
    }
    float inv = 1.0f / sum;
    #pragma unroll
    for (int i = 0; i < 64; i++) base[i << 12] = vals[i] * inv;
}

// ---------------- agg = V A^T, write into g_agg -----------------------------
__global__ void __launch_bounds__(256) av_kernel(const float* __restrict__ S,
                                                 const float* __restrict__ qkv,
                                                 float* __restrict__ agg) {
    int blk = blockIdx.x; // b*512 + hi
    int b = blk >> 9;
    int hi = blk & 511;
    const float* A = S + ((size_t)blk << 12);
    const float* V = qkv + (((size_t)(b * 1536 + 1024 + hi)) << 12);

    __shared__ float As_[64][65];
    __shared__ float Vs[64][65];
    int tid = threadIdx.x;
    #pragma unroll
    for (int it = 0; it < 16; it++) {
        int i = tid + it * 256;
        int r = i >> 6, cc = i & 63;
        As_[r][cc] = A[i];
        Vs[r][cc] = V[i];
    }
    __syncthreads();

    int tw = tid & 15, td = tid >> 4;
    float acc[4][4];
    #pragma unroll
    for (int r = 0; r < 4; r++)
        #pragma unroll
        for (int cc = 0; cc < 4; cc++) acc[r][cc] = 0.0f;

    #pragma unroll 4
    for (int W = 0; W < 64; W++) {
        float v[4], a[4];
        #pragma unroll
        for (int r = 0; r < 4; r++) v[r] = Vs[td * 4 + r][W];
        #pragma unroll
        for (int cc = 0; cc < 4; cc++) a[cc] = As_[tw * 4 + cc][W];
        #pragma unroll
        for (int r = 0; r < 4; r++)
            #pragma unroll
            for (int cc = 0; cc < 4; cc++) acc[r][cc] += v[r] * a[cc];
    }
    float* outp = agg + (((size_t)(b * 512 + hi)) << 12);
    #pragma unroll
    for (int r = 0; r < 4; r++)
        #pragma unroll
        for (int cc = 0; cc < 4; cc++)
            outp[(td * 4 + r) * 64 + tw * 4 + cc] = acc[r][cc];
}

// ------------------------- BatchNorm stats + SiLU ---------------------------
__global__ void bn_stats(const float* __restrict__ y, float* __restrict__ mean,
                         float* __restrict__ var) {
    __shared__ float sh[8];
    int c = blockIdx.x;
    float s = 0.0f, s2 = 0.0f;
    for (int i = threadIdx.x; i < BATCH * HW; i += blockDim.x) {
        int b = i >> 12, p = i & 4095;
        float v = y[(((size_t)(b * 512 + c)) << 12) + p];
        s += v; s2 += v * v;
    }
    s = block_reduce_sum_256(s, sh);
    s2 = block_reduce_sum_256(s2, sh);
    if (threadIdx.x == 0) {
        float m = s * (1.0f / 32768.0f);
        mean[c] = m;
        var[c] = s2 * (1.0f / 32768.0f) - m * m;
    }
}

__global__ void bn_silu(const float* __restrict__ y, const float* __restrict__ mean,
                        const float* __restrict__ var, const float* __restrict__ g,
                        const float* __restrict__ bta, float* __restrict__ out) {
    int idx = blockIdx.x * blockDim.x + threadIdx.x;
    int c = (idx >> 12) & 511;
    float v = (y[idx] - mean[c]) * rsqrtf(var[c] + 1e-5f) * g[c] + bta[c];
    out[idx] = v * sigmoidf_(v);
}

// ------------------------------- launcher -----------------------------------
static float* sym_addr(const void* symbol) {
    void* p = nullptr;
    cudaGetSymbolAddress(&p, symbol);
    return (float*)p;
}

extern "C" void kernel_launch(void* const* d_in, const int* in_sizes, int n_in,
                              void* d_out, int out_size) {
    const float* x       = (const float*)d_in[0];
    const float* box_w1  = (const float*)d_in[1];
    const float* box_b1  = (const float*)d_in[2];
    const float* box_w2  = (const float*)d_in[3];
    const float* box_b2  = (const float*)d_in[4];
    const float* edge_w1 = (const float*)d_in[5];
    const float* edge_b1 = (const float*)d_in[6];
    const float* gn_g    = (const float*)d_in[7];
    const float* gn_b    = (const float*)d_in[8];
    const float* edge_w2 = (const float*)d_in[9];
    const float* edge_b2 = (const float*)d_in[10];
    const float* qkv_w   = (const float*)d_in[11];
    const float* qkv_b   = (const float*)d_in[12];
    const float* fus_w   = (const float*)d_in[13];
    const float* fus_b   = (const float*)d_in[14];
    const float* bn_g    = (const float*)d_in[15];
    const float* bn_b    = (const float*)d_in[16];
    float* out = (float*)d_out;

    float* wt_box1  = sym_addr(g_wt_box1);
    float* wt_edge1 = sym_addr(g_wt_edge1);
    float* wt_qkv   = sym_addr(g_wt_qkv);
    float* wt_fus   = sym_addr(g_wt_fus);
    float* t1       = sym_addr(g_t1);
    float* boxes    = sym_addr(g_boxes);
    float* e1       = sym_addr(g_e1);
    float* edge     = sym_addr(g_edge);
    float* qkvbuf   = sym_addr(g_qkv);
    float* Sbuf     = sym_addr(g_S);
    float* aggbuf   = sym_addr(g_agg);
    float* ybuf     = sym_addr(g_y);
    float* bnmean   = sym_addr(g_bnmean);
    float* bnvar    = sym_addr(g_bnvar);

    dim3 tb(32, 32);
    transpose_w<<<dim3(144, 2), tb>>>(box_w1, wt_box1, 64, 4608);
    transpose_w<<<dim3(2, 2), tb>>>(edge_w1, wt_edge1, 64, 36);
    transpose_w<<<dim3(16, 48), tb>>>(qkv_w, wt_qkv, 1536, 512);
    transpose_w<<<dim3(288, 16), tb>>>(fus_w, wt_fus, 512, 9216);

    // box_net: conv3x3(512->64)+GELU -> conv1x1(64->4)+sigmoid
    conv_mma<64, 128, 32, 32, 3><<<dim3(256, 1), 256>>>(
        x, x, 512, wt_box1, box_b1, t1, 512, 64, /*gelu*/1);
    conv1x1_small<4, 64><<<128, 256>>>(t1, box_w2, box_b2, boxes, /*sigmoid*/2);

    // edge_net: conv3x3(4->64) -> GN+GELU -> conv1x1(64->8)
    conv_mma<64, 128, 32, 32, 3><<<dim3(256, 1), 256>>>(
        boxes, boxes, 4, wt_edge1, edge_b1, e1, 4, 64, 0);
    groupnorm_gelu<<<64, 256>>>(e1, gn_g, gn_b);
    conv1x1_small<8, 64><<<128, 256>>>(e1, edge_w2, edge_b2, edge, 0);

    // qkv 1x1 conv (512 -> 1536)
    conv_mma<128, 128, 64, 32, 1><<<dim3(256, 12), 256>>>(
        x, x, 512, wt_qkv, qkv_b, qkvbuf, 512, 1536, 0);

    // attention
    qk_kernel<<<4096, 256>>>(qkvbuf, edge, Sbuf);
    softmax_i<<<1024, 256>>>(Sbuf);
    av_kernel<<<4096, 256>>>(Sbuf, qkvbuf, aggbuf);

    // fusion conv3x3 (x | agg : 1024 -> 512) + BN + SiLU
    conv_mma<128, 128, 64, 32, 3><<<dim3(256, 4), 256>>>(
        x, aggbuf, 512, wt_fus, fus_b, ybuf, 1024, 512, 0);
    bn_stats<<<512, 256>>>(ybuf, bnmean, bnvar);
    bn_silu<<<65536, 256>>>(ybuf, bnmean, bnvar, bn_g, bn_b, out);
}

// round 4
// speedup vs baseline: 1.7176x; 1.3367x over previous
#include <cuda_runtime.h>
#include <math.h>
#include <stdint.h>

// ---------------------------------------------------------------------------
// AutoBoxGraphAttention: B=8, C=512, H=W=64, NH=8, HD=64
// Round 4: tf32 mma convs with (a) weights pre-packed to fragment-native tf32
// layout in gmem -> A-fill is two cp.async 16B copies; (b) K reordered as
// r*Cin+ci (Cin pow2) -> im2col index math is shifts/masks, no division.
// ---------------------------------------------------------------------------

#define BATCH 8
#define HW 4096   // 64*64

// ------------------------- device scratch buffers --------------------------
__device__ __align__(16) uint32_t g_wtf_box1[4608 * 64];
__device__ __align__(16) uint32_t g_wtf_edge1[48 * 64];
__device__ __align__(16) uint32_t g_wtf_qkv[512 * 1536];
__device__ __align__(16) uint32_t g_wtf_fus[9216 * 512];
__device__ float g_t1[BATCH * 64 * HW];
__device__ float g_boxes[BATCH * 4 * HW];
__device__ float g_e1[BATCH * 64 * HW];
__device__ float g_edge[BATCH * 8 * HW];
__device__ float g_qkv[BATCH * 1536 * HW];   // 192 MB
__device__ float g_S[BATCH * 8 * 64 * HW];   // 67 MB  S[b,h,i,w,W]
__device__ float g_agg[BATCH * 512 * HW];
__device__ float g_y[BATCH * 512 * HW];
__device__ float g_bnmean[512];
__device__ float g_bnvar[512];

// ------------------------------ helpers ------------------------------------
__device__ __forceinline__ float gelu_exact(float v) {
    return 0.5f * v * (1.0f + erff(v * 0.70710678118654752f));
}
__device__ __forceinline__ float sigmoidf_(float v) {
    return 1.0f / (1.0f + expf(-v));
}
template<int ACT>
__device__ __forceinline__ float apply_act(float v) {
    if (ACT == 1) return gelu_exact(v);
    if (ACT == 2) return sigmoidf_(v);
    return v;
}
__device__ __forceinline__ uint32_t f2tf32(float v) {
    uint32_t u;
    asm("cvt.rna.tf32.f32 %0, %1;" : "=r"(u) : "f"(v));
    return u;
}
__device__ __forceinline__ void mma_tf32(float c[4], const uint32_t a[4],
                                         const uint32_t b[2]) {
    asm volatile(
        "mma.sync.aligned.m16n8k8.row.col.f32.tf32.tf32.f32 "
        "{%0,%1,%2,%3}, {%4,%5,%6,%7}, {%8,%9}, {%0,%1,%2,%3};"
        : "+f"(c[0]), "+f"(c[1]), "+f"(c[2]), "+f"(c[3])
        : "r"(a[0]), "r"(a[1]), "r"(a[2]), "r"(a[3]), "r"(b[0]), "r"(b[1]));
}
__device__ __forceinline__ void cp_async16(uint32_t smem_addr, const void* gptr) {
    asm volatile("cp.async.ca.shared.global [%0], [%1], 16;"
                 :: "r"(smem_addr), "l"(gptr));
}
__device__ __forceinline__ void cp_async_wait_all() {
    asm volatile("cp.async.commit_group;\n\tcp.async.wait_group 0;" ::: "memory");
}

// block reduce for 256 threads (8 warps); sh must hold >= 8 floats
__device__ __forceinline__ float block_reduce_sum_256(float v, float* sh) {
    #pragma unroll
    for (int o = 16; o; o >>= 1) v += __shfl_xor_sync(0xffffffffu, v, o);
    int w = threadIdx.x >> 5;
    if ((threadIdx.x & 31) == 0) sh[w] = v;
    __syncthreads();
    float r = 0.0f;
    if (threadIdx.x < 8) {
        r = sh[threadIdx.x];
        #pragma unroll
        for (int o = 4; o; o >>= 1) r += __shfl_xor_sync(0xffu, r, o);
    }
    if (threadIdx.x == 0) sh[0] = r;
    __syncthreads();
    float out = sh[0];
    __syncthreads();
    return out;
}

// ------------------- weight prep: fragment-native tf32 ----------------------
// Input  w[co][ci*RRtot + rr] (OIHW flattened).
// K reordered: kg = rr*Cin + ci  (Cin pow2).  Output layout (u32):
//   wtf[((kt*(Cout/16)+mtile)*2 + ks)*128 + (g*4+t)*4 + jb]
// where kt=kg>>4, kin=kg&15, ks=kin>>3, t=kin&3, kbit=(kin>>2)&1;
//       mtile=co>>4, rm=co&15, g=rm&7, rbit=(rm>>3)&1, jb=rbit|(kbit<<1).
__global__ void prep_w(const float* __restrict__ w, uint32_t* __restrict__ wtf,
                       int Cout, int Cin, int RRtot, int log2Cin, int KtotPad) {
    int idx = blockIdx.x * blockDim.x + threadIdx.x;
    if (idx >= Cout * KtotPad) return;
    int co = idx / KtotPad;
    int kg = idx - co * KtotPad;
    int rr = kg >> log2Cin;
    int ci = kg & (Cin - 1);
    float v = (rr < RRtot) ? w[(co * Cin + ci) * RRtot + rr] : 0.0f;
    int kt = kg >> 4, kin = kg & 15;
    int ks = kin >> 3, t = kin & 3, kbit = (kin >> 2) & 1;
    int mtile = co >> 4, rm = co & 15;
    int g = rm & 7, rbit = (rm >> 3) & 1;
    int jb = rbit | (kbit << 1);
    wtf[((kt * (Cout >> 4) + mtile) * 2 + ks) * 128 + (g * 4 + t) * 4 + jb] = f2tf32(v);
}

// ------------------ implicit-GEMM conv on tensor cores (tf32) ---------------
// K order: kg = r*CIN + ci (r = filter tap 0..R*R-1). A pre-packed in gmem.
template<int BM, int BN, int WM, int WN, int R, int CIN, int LOG2CIN,
         bool SPLIT, int ACT>
__global__ void __launch_bounds__(256)
conv_mma(const float* __restrict__ in0, const float* __restrict__ in1,
         const uint32_t* __restrict__ wtf, const float* __restrict__ bias,
         float* __restrict__ out, int Cout) {
    constexpr int BK = 16;
    constexpr int WARPS_N = BN / WN;
    constexpr int MT = WM / 16;
    constexpr int NT = WN / 8;
    constexpr int RRtot = R * R;
    constexpr int Ktot = CIN * RRtot;
    constexpr int KtotPad = (Ktot + 15) & ~15;
    constexpr int CSPLIT = SPLIT ? CIN / 2 : CIN;

    const int tid = threadIdx.x;
    const int lane = tid & 31;
    const int w = tid >> 5;
    const int wm = w / WARPS_N;
    const int wn = w % WARPS_N;

    const int m0 = blockIdx.y * BM;
    const int n0 = blockIdx.x * BN;
    const int b = n0 >> 12;
    const int p0 = n0 & 4095;
    const int y0 = p0 >> 6;

    __shared__ __align__(16) uint32_t As[BM * BK];
    __shared__ __align__(16) uint32_t Bs[BN * BK];
    const uint32_t As_sm = (uint32_t)__cvta_generic_to_shared(As);

    float c[MT][NT][4];
    #pragma unroll
    for (int i = 0; i < MT; i++)
        #pragma unroll
        for (int j = 0; j < NT; j++)
            #pragma unroll
            for (int q = 0; q < 4; q++) c[i][j][q] = 0.0f;

    for (int kt = 0; kt < KtotPad / BK; kt++) {
        const int k0 = kt * BK;
        // ---- A: straight async copy of pre-packed fragment block ----
        {
            const uint32_t* src = wtf + (kt * (Cout >> 4) + (m0 >> 4)) * 256;
            #pragma unroll
            for (int it = 0; it < (BM * BK) / (256 * 4); it++) {
                int i4 = tid + it * 256;
                cp_async16(As_sm + i4 * 16, src + i4 * 4);
            }
        }
        // ---- B: im2col gather, scatter to fragment slots ----
        #pragma unroll
        for (int it = 0; it < (BN * BK) / 256; it++) {
            int i = tid + it * 256;
            int n = i & (BN - 1);
            int k = i / BN;
            int kk = k0 + k;
            int r = kk >> LOG2CIN;
            int ci = kk & (CIN - 1);
            float v = 0.0f;
            if (R == 1) {
                const float* base = in0 + (((size_t)(b * CIN + ci)) << 12);
                v = base[(y0 << 6) + n];
            } else {
                int ky = (r * 11) >> 5;       // r/3 for r<10
                int kx = r - ky * 3;
                int sy = y0 + (n >> 6) + ky - 1;
                int sx = (n & 63) + kx - 1;
                bool ok = (r < RRtot) & ((unsigned)sy < 64u) & ((unsigned)sx < 64u);
                if (ok) {
                    const float* base;
                    if (SPLIT && ci >= CSPLIT)
                        base = in1 + (((size_t)(b * (CIN - CSPLIT) + (ci - CSPLIT))) << 12);
                    else
                        base = in0 + (((size_t)(b * CSPLIT + ci)) << 12);
                    v = base[(sy << 6) + sx];
                }
            }
            int nt = n >> 3, gg = n & 7;
            int t = k & 3, j = (k >> 2) & 1, ks = k >> 3;
            Bs[(((nt * 2 + ks) * 32) + gg * 4 + t) * 2 + j] = f2tf32(v);
        }
        cp_async_wait_all();
        __syncthreads();

        #pragma unroll
        for (int ks = 0; ks < 2; ks++) {
            uint32_t af[MT][4];
            uint32_t bf[NT][2];
            #pragma unroll
            for (int mt = 0; mt < MT; mt++) {
                uint4 t4 = ((const uint4*)As)[((wm * MT + mt) * 2 + ks) * 32 + lane];
                af[mt][0] = t4.x; af[mt][1] = t4.y; af[mt][2] = t4.z; af[mt][3] = t4.w;
            }
            #pragma unroll
            for (int nt = 0; nt < NT; nt++) {
                uint2 t2 = ((const uint2*)Bs)[((wn * NT + nt) * 2 + ks) * 32 + lane];
                bf[nt][0] = t2.x; bf[nt][1] = t2.y;
            }
            #pragma unroll
            for (int mt = 0; mt < MT; mt++)
                #pragma unroll
                for (int nt = 0; nt < NT; nt++)
                    mma_tf32(c[mt][nt], af[mt], bf[nt]);
        }
        __syncthreads();
    }

    // ---- epilogue ----
    const int g = lane >> 2, t = lane & 3;
    #pragma unroll
    for (int mt = 0; mt < MT; mt++) {
        int row0 = m0 + wm * WM + mt * 16 + g;
        float bs0 = bias[row0];
        float bs1 = bias[row0 + 8];
        #pragma unroll
        for (int nt = 0; nt < NT; nt++) {
            int p = p0 + wn * WN + nt * 8 + t * 2;
            float2 o0, o1;
            o0.x = apply_act<ACT>(c[mt][nt][0] + bs0);
            o0.y = apply_act<ACT>(c[mt][nt][1] + bs0);
            o1.x = apply_act<ACT>(c[mt][nt][2] + bs1);
            o1.y = apply_act<ACT>(c[mt][nt][3] + bs1);
            *(float2*)&out[(((size_t)(b * Cout + row0)) << 12) + p] = o0;
            *(float2*)&out[(((size_t)(b * Cout + row0 + 8)) << 12) + p] = o1;
        }
    }
}

// ------------------------ small 1x1 conv (Cout tiny) -------------------------
template<int COUT, int CIN, int ACT>
__global__ void conv1x1_small(const float* __restrict__ in, const float* __restrict__ w,
                              const float* __restrict__ bias, float* __restrict__ out) {
    __shared__ float ws[COUT * CIN];
    for (int i = threadIdx.x; i < COUT * CIN; i += blockDim.x) ws[i] = w[i];
    __syncthreads();
    int idx = blockIdx.x * blockDim.x + threadIdx.x;
    if (idx >= BATCH * HW) return;
    int b = idx >> 12, p = idx & 4095;
    float acc[COUT];
    #pragma unroll
    for (int co = 0; co < COUT; co++) acc[co] = bias[co];
    for (int ci = 0; ci < CIN; ci++) {
        float v = in[((b * CIN + ci) << 12) + p];
        #pragma unroll
        for (int co = 0; co < COUT; co++) acc[co] += ws[co * CIN + ci] * v;
    }
    #pragma unroll
    for (int co = 0; co < COUT; co++)
        out[((b * COUT + co) << 12) + p] = apply_act<ACT>(acc[co]);
}

// ---------------------- GroupNorm(8 groups of 8ch) + GELU -------------------
__global__ void groupnorm_gelu(float* __restrict__ e, const float* __restrict__ g,
                               const float* __restrict__ bta) {
    __shared__ float sh[8];
    int b = blockIdx.x >> 3, grp = blockIdx.x & 7;
    const int base = (b * 64 + grp * 8) << 12;
    float s = 0.0f, s2 = 0.0f;
    for (int i = threadIdx.x; i < 8 * HW; i += blockDim.x) {
        float v = e[base + i];
        s += v; s2 += v * v;
    }
    s = block_reduce_sum_256(s, sh);
    s2 = block_reduce_sum_256(s2, sh);
    float mean = s * (1.0f / 32768.0f);
    float var = s2 * (1.0f / 32768.0f) - mean * mean;
    float rstd = rsqrtf(var + 1e-5f);
    for (int i = threadIdx.x; i < 8 * HW; i += blockDim.x) {
        int ch = grp * 8 + (i >> 12);
        float v = (e[base + i] - mean) * rstd * g[ch] + bta[ch];
        e[base + i] = gelu_exact(v);
    }
}

// ---------------------- attention: S = Q^T K / 8 + edge ---------------------
__global__ void __launch_bounds__(256) qk_kernel(const float* __restrict__ qkv,
                                                 const float* __restrict__ edge,
                                                 float* __restrict__ S) {
    int blk = blockIdx.x;           // b*512 + h*64 + i
    int b = blk >> 9;
    int hi = blk & 511;
    const float* Q = qkv + (((size_t)(b * 1536 + hi)) << 12);
    const float* K = qkv + (((size_t)(b * 1536 + 512 + hi)) << 12);
    const float* E = edge + ((size_t)blk << 6);

    __shared__ float Qs[64 * 64];
    __shared__ float Ks[64 * 64];
    __shared__ float Es[64];
    int tid = threadIdx.x;
    #pragma unroll
    for (int it = 0; it < 4; it++) {
        int i = tid + it * 256;
        ((float4*)Qs)[i] = ((const float4*)Q)[i];
        ((float4*)Ks)[i] = ((const float4*)K)[i];
    }
    if (tid < 64) Es[tid] = E[tid];
    __syncthreads();

    int tW = tid & 15, tw = tid >> 4;
    float acc[4][4];
    #pragma unroll
    for (int r = 0; r < 4; r++)
        #pragma unroll
        for (int c = 0; c < 4; c++) acc[r][c] = 0.0f;

    #pragma unroll 4
    for (int d = 0; d < 64; d++) {
        float4 qv = *(const float4*)&Qs[d * 64 + tw * 4];
        float4 kv = *(const float4*)&Ks[d * 64 + tW * 4];
        float qa[4] = {qv.x, qv.y, qv.z, qv.w};
        float ka[4] = {kv.x, kv.y, kv.z, kv.w};
        #pragma unroll
        for (int r = 0; r < 4; r++)
            #pragma unroll
            for (int c = 0; c < 4; c++) acc[r][c] += qa[r] * ka[c];
    }
    float* So = S + ((size_t)blk << 12);
    #pragma unroll
    for (int r = 0; r < 4; r++) {
        int ww = tw * 4 + r;
        float e = Es[ww];
        #pragma unroll
        for (int c = 0; c < 4; c++)
            So[ww * 64 + tW * 4 + c] = acc[r][c] * 0.125f + e;
    }
}

// ------------------- softmax over i (stride 4096 within bh) -----------------
__global__ void __launch_bounds__(256) softmax_i(float* __restrict__ S) {
    int col = blockIdx.x * blockDim.x + threadIdx.x;
    if (col >= 64 * HW) return;
    int bh = col >> 12, p = col & 4095;
    float* base = S + ((size_t)bh << 18) + p;
    float vals[64];
    float mx = -3.0e38f;
    #pragma unroll
    for (int i = 0; i < 64; i++) {
        vals[i] = base[i << 12];
        mx = fmaxf(mx, vals[i]);
    }
    float sum = 0.0f;
    #pragma unroll
    for (int i = 0; i < 64; i++) {
        vals[i] = expf(vals[i] - mx);
        sum += vals[i];
    }
    float inv = 1.0f / sum;
    #pragma unroll
    for (int i = 0; i < 64; i++) base[i << 12] = vals[i] * inv;
}

// ---------------- agg = V A^T, write into g_agg -----------------------------
__global__ void __launch_bounds__(256) av_kernel(const float* __restrict__ S,
                                                 const float* __restrict__ qkv,
                                                 float* __restrict__ agg) {
    int blk = blockIdx.x; // b*512 + hi
    int b = blk >> 9;
    int hi = blk & 511;
    const float* A = S + ((size_t)blk << 12);
    const float* V = qkv + (((size_t)(b * 1536 + 1024 + hi)) << 12);

    __shared__ float As_[64][65];
    __shared__ float Vs[64][65];
    int tid = threadIdx.x;
    #pragma unroll
    for (int it = 0; it < 16; it++) {
        int i = tid + it * 256;
        int r = i >> 6, cc = i & 63;
        As_[r][cc] = A[i];
        Vs[r][cc] = V[i];
    }
    __syncthreads();

    int tw = tid & 15, td = tid >> 4;
    float acc[4][4];
    #pragma unroll
    for (int r = 0; r < 4; r++)
        #pragma unroll
        for (int cc = 0; cc < 4; cc++) acc[r][cc] = 0.0f;

    #pragma unroll 4
    for (int W = 0; W < 64; W++) {
        float v[4], a[4];
        #pragma unroll
        for (int r = 0; r < 4; r++) v[r] = Vs[td * 4 + r][W];
        #pragma unroll
        for (int cc = 0; cc < 4; cc++) a[cc] = As_[tw * 4 + cc][W];
        #pragma unroll
        for (int r = 0; r < 4; r++)
            #pragma unroll
            for (int cc = 0; cc < 4; cc++) acc[r][cc] += v[r] * a[cc];
    }
    float* outp = agg + (((size_t)(b * 512 + hi)) << 12);
    #pragma unroll
    for (int r = 0; r < 4; r++)
        #pragma unroll
        for (int cc = 0; cc < 4; cc++)
            outp[(td * 4 + r) * 64 + tw * 4 + cc] = acc[r][cc];
}

// ------------------------- BatchNorm stats + SiLU ---------------------------
__global__ void bn_stats(const float* __restrict__ y, float* __restrict__ mean,
                         float* __restrict__ var) {
    __shared__ float sh[8];
    int c = blockIdx.x;
    float s = 0.0f, s2 = 0.0f;
    for (int i = threadIdx.x; i < BATCH * HW; i += blockDim.x) {
        int b = i >> 12, p = i & 4095;
        float v = y[(((size_t)(b * 512 + c)) << 12) + p];
        s += v; s2 += v * v;
    }
    s = block_reduce_sum_256(s, sh);
    s2 = block_reduce_sum_256(s2, sh);
    if (threadIdx.x == 0) {
        float m = s * (1.0f / 32768.0f);
        mean[c] = m;
        var[c] = s2 * (1.0f / 32768.0f) - m * m;
    }
}

__global__ void bn_silu(const float* __restrict__ y, const float* __restrict__ mean,
                        const float* __restrict__ var, const float* __restrict__ g,
                        const float* __restrict__ bta, float* __restrict__ out) {
    int idx = blockIdx.x * blockDim.x + threadIdx.x;
    int c = (idx >> 12) & 511;
    float v = (y[idx] - mean[c]) * rsqrtf(var[c] + 1e-5f) * g[c] + bta[c];
    out[idx] = v * sigmoidf_(v);
}

// ------------------------------- launcher -----------------------------------
static void* sym_addr(const void* symbol) {
    void* p = nullptr;
    cudaGetSymbolAddress(&p, symbol);
    return p;
}

extern "C" void kernel_launch(void* const* d_in, const int* in_sizes, int n_in,
                              void* d_out, int out_size) {
    const float* x       = (const float*)d_in[0];
    const float* box_w1  = (const float*)d_in[1];
    const float* box_b1  = (const float*)d_in[2];
    const float* box_w2  = (const float*)d_in[3];
    const float* box_b2  = (const float*)d_in[4];
    const float* edge_w1 = (const float*)d_in[5];
    const float* edge_b1 = (const float*)d_in[6];
    const float* gn_g    = (const float*)d_in[7];
    const float* gn_b    = (const float*)d_in[8];
    const float* edge_w2 = (const float*)d_in[9];
    const float* edge_b2 = (const float*)d_in[10];
    const float* qkv_w   = (const float*)d_in[11];
    const float* qkv_b   = (const float*)d_in[12];
    const float* fus_w   = (const float*)d_in[13];
    const float* fus_b   = (const float*)d_in[14];
    const float* bn_g    = (const float*)d_in[15];
    const float* bn_b    = (const float*)d_in[16];
    float* out = (float*)d_out;

    uint32_t* wtf_box1  = (uint32_t*)sym_addr(g_wtf_box1);
    uint32_t* wtf_edge1 = (uint32_t*)sym_addr(g_wtf_edge1);
    uint32_t* wtf_qkv   = (uint32_t*)sym_addr(g_wtf_qkv);
    uint32_t* wtf_fus   = (uint32_t*)sym_addr(g_wtf_fus);
    float* t1       = (float*)sym_addr(g_t1);
    float* boxes    = (float*)sym_addr(g_boxes);
    float* e1       = (float*)sym_addr(g_e1);
    float* edge     = (float*)sym_addr(g_edge);
    float* qkvbuf   = (float*)sym_addr(g_qkv);
    float* Sbuf     = (float*)sym_addr(g_S);
    float* aggbuf   = (float*)sym_addr(g_agg);
    float* ybuf     = (float*)sym_addr(g_y);
    float* bnmean   = (float*)sym_addr(g_bnmean);
    float* bnvar    = (float*)sym_addr(g_bnvar);

    // weight prep (fragment-native tf32, K = r*Cin + ci)
    prep_w<<<(64 * 4608 + 255) / 256, 256>>>(box_w1, wtf_box1, 64, 512, 9, 9, 4608);
    prep_w<<<(64 * 48 + 255) / 256, 256>>>(edge_w1, wtf_edge1, 64, 4, 9, 2, 48);
    prep_w<<<(1536 * 512 + 255) / 256, 256>>>(qkv_w, wtf_qkv, 1536, 512, 1, 9, 512);
    prep_w<<<(512 * 9216 + 255) / 256, 256>>>(fus_w, wtf_fus, 512, 1024, 9, 10, 9216);

    // box_net: conv3x3(512->64)+GELU -> conv1x1(64->4)+sigmoid
    conv_mma<64, 128, 32, 32, 3, 512, 9, false, 1><<<dim3(256, 1), 256>>>(
        x, x, wtf_box1, box_b1, t1, 64);
    conv1x1_small<4, 64, 2><<<128, 256>>>(t1, box_w2, box_b2, boxes);

    // edge_net: conv3x3(4->64) -> GN+GELU -> conv1x1(64->8)
    conv_mma<64, 128, 32, 32, 3, 4, 2, false, 0><<<dim3(256, 1), 256>>>(
        boxes, boxes, wtf_edge1, edge_b1, e1, 64);
    groupnorm_gelu<<<64, 256>>>(e1, gn_g, gn_b);
    conv1x1_small<8, 64, 0><<<128, 256>>>(e1, edge_w2, edge_b2, edge);

    // qkv 1x1 conv (512 -> 1536)
    conv_mma<128, 128, 64, 32, 1, 512, 9, false, 0><<<dim3(256, 12), 256>>>(
        x, x, wtf_qkv, qkv_b, qkvbuf, 1536);

    // attention
    qk_kernel<<<4096, 256>>>(qkvbuf, edge, Sbuf);
    softmax_i<<<1024, 256>>>(Sbuf);
    av_kernel<<<4096, 256>>>(Sbuf, qkvbuf, aggbuf);

    // fusion conv3x3 (x | agg : 1024 -> 512) + BN + SiLU
    conv_mma<128, 128, 64, 32, 3, 1024, 10, true, 0><<<dim3(256, 4), 256>>>(
        x, aggbuf, wtf_fus, fus_b, ybuf, 512);
    bn_stats<<<512, 256>>>(ybuf, bnmean, bnvar);
    bn_silu<<<65536, 256>>>(ybuf, bnmean, bnvar, bn_g, bn_b, out);
}

// round 5
// speedup vs baseline: 6.0259x; 3.5083x over previous
#include <cuda_runtime.h>
#include <math.h>
#include <stdint.h>

// ---------------------------------------------------------------------------
// AutoBoxGraphAttention: B=8, C=512, H=W=64, NH=8, HD=64
// Round 5: conv mainloop feeds MMA B-fragments directly from a padded input
// window in smem (loaded once per 16-channel group via cp.async, all 9 taps
// reuse it). K order: (channel-group, tap, ci_in). A prepacked + double-buffed.
// ---------------------------------------------------------------------------

#define BATCH 8
#define HW 4096   // 64*64

// ------------------------- device scratch buffers --------------------------
__device__ __align__(16) uint32_t g_wtf_box1[4608 * 64];
__device__ __align__(16) uint32_t g_wtf_edge1[48 * 64];
__device__ __align__(16) uint32_t g_wtf_qkv[512 * 1536];
__device__ __align__(16) uint32_t g_wtf_fus[9216 * 512];
__device__ float g_t1[BATCH * 64 * HW];
__device__ float g_boxes[BATCH * 4 * HW];
__device__ float g_e1[BATCH * 64 * HW];
__device__ float g_edge[BATCH * 8 * HW];
__device__ float g_qkv[BATCH * 1536 * HW];   // 192 MB
__device__ float g_S[BATCH * 8 * 64 * HW];   // 67 MB  S[b,h,i,w,W]
__device__ float g_agg[BATCH * 512 * HW];
__device__ float g_y[BATCH * 512 * HW];
__device__ float g_bnmean[512];
__device__ float g_bnvar[512];

// ------------------------------ helpers ------------------------------------
__device__ __forceinline__ float gelu_exact(float v) {
    return 0.5f * v * (1.0f + erff(v * 0.70710678118654752f));
}
__device__ __forceinline__ float sigmoidf_(float v) {
    return 1.0f / (1.0f + expf(-v));
}
template<int ACT>
__device__ __forceinline__ float apply_act(float v) {
    if (ACT == 1) return gelu_exact(v);
    if (ACT == 2) return sigmoidf_(v);
    return v;
}
__device__ __forceinline__ uint32_t f2tf32(float v) {
    uint32_t u;
    asm("cvt.rna.tf32.f32 %0, %1;" : "=r"(u) : "f"(v));
    return u;
}
__device__ __forceinline__ void mma_tf32(float c[4], const uint32_t a[4],
                                         const uint32_t b[2]) {
    asm volatile(
        "mma.sync.aligned.m16n8k8.row.col.f32.tf32.tf32.f32 "
        "{%0,%1,%2,%3}, {%4,%5,%6,%7}, {%8,%9}, {%0,%1,%2,%3};"
        : "+f"(c[0]), "+f"(c[1]), "+f"(c[2]), "+f"(c[3])
        : "r"(a[0]), "r"(a[1]), "r"(a[2]), "r"(a[3]), "r"(b[0]), "r"(b[1]));
}
__device__ __forceinline__ void cp_async16(uint32_t smem_addr, const void* gptr) {
    asm volatile("cp.async.ca.shared.global [%0], [%1], 16;"
                 :: "r"(smem_addr), "l"(gptr));
}
__device__ __forceinline__ void cp_async16z(uint32_t smem_addr, const void* gptr,
                                            uint32_t src_bytes) {
    asm volatile("cp.async.ca.shared.global [%0], [%1], 16, %2;"
                 :: "r"(smem_addr), "l"(gptr), "r"(src_bytes));
}
__device__ __forceinline__ void cp_async_commit() {
    asm volatile("cp.async.commit_group;" ::: "memory");
}
template<int N>
__device__ __forceinline__ void cp_async_wait() {
    asm volatile("cp.async.wait_group %0;" :: "n"(N) : "memory");
}

// block reduce for 256 threads (8 warps); sh must hold >= 8 floats
__device__ __forceinline__ float block_reduce_sum_256(float v, float* sh) {
    #pragma unroll
    for (int o = 16; o; o >>= 1) v += __shfl_xor_sync(0xffffffffu, v, o);
    int w = threadIdx.x >> 5;
    if ((threadIdx.x & 31) == 0) sh[w] = v;
    __syncthreads();
    float r = 0.0f;
    if (threadIdx.x < 8) {
        r = sh[threadIdx.x];
        #pragma unroll
        for (int o = 4; o; o >>= 1) r += __shfl_xor_sync(0xffu, r, o);
    }
    if (threadIdx.x == 0) sh[0] = r;
    __syncthreads();
    float out = sh[0];
    __syncthreads();
    return out;
}

// ------------- weight prep, grouped K order: kg=((ci>>4)*RR+rr)*16+(ci&15) --
__global__ void prep_wg(const float* __restrict__ w, uint32_t* __restrict__ wtf,
                        int Cout, int Cin, int RRtot) {
    int idx = blockIdx.x * blockDim.x + threadIdx.x;
    if (idx >= Cout * Cin * RRtot) return;
    int co = idx / (Cin * RRtot);
    int rem = idx - co * (Cin * RRtot);
    int ci = rem / RRtot;
    int rr = rem - ci * RRtot;
    float v = w[idx];
    int kt = (ci >> 4) * RRtot + rr;
    int kin = ci & 15;
    int ks = kin >> 3, t = kin & 3, kbit = (kin >> 2) & 1;
    int mtile = co >> 4, rm = co & 15;
    int g = rm & 7, rbit = (rm >> 3) & 1;
    int jb = rbit | (kbit << 1);
    wtf[((kt * (Cout >> 4) + mtile) * 2 + ks) * 128 + (g * 4 + t) * 4 + jb] = f2tf32(v);
}

// ------------- weight prep, old order kg = rr*Cin + ci (edge conv) ----------
__global__ void prep_w(const float* __restrict__ w, uint32_t* __restrict__ wtf,
                       int Cout, int Cin, int RRtot, int log2Cin, int KtotPad) {
    int idx = blockIdx.x * blockDim.x + threadIdx.x;
    if (idx >= Cout * KtotPad) return;
    int co = idx / KtotPad;
    int kg = idx - co * KtotPad;
    int rr = kg >> log2Cin;
    int ci = kg & (Cin - 1);
    float v = (rr < RRtot) ? w[(co * Cin + ci) * RRtot + rr] : 0.0f;
    int kt = kg >> 4, kin = kg & 15;
    int ks = kin >> 3, t = kin & 3, kbit = (kin >> 2) & 1;
    int mtile = co >> 4, rm = co & 15;
    int g = rm & 7, rbit = (rm >> 3) & 1;
    int jb = rbit | (kbit << 1);
    wtf[((kt * (Cout >> 4) + mtile) * 2 + ks) * 128 + (g * 4 + t) * 4 + jb] = f2tf32(v);
}

// ---------------- window-based implicit-GEMM conv (tf32 mma) ----------------
// BN=128 (2 output rows), WN=32. Window: 16 ch x ROWS rows x 64 cols padded.
template<int BM, int WM, int R, int CIN, bool SPLIT, int ACT>
__global__ void __launch_bounds__(256)
conv_win(const float* __restrict__ in0, const float* __restrict__ in1,
         const uint32_t* __restrict__ wtf, const float* __restrict__ bias,
         float* __restrict__ out, int Cout) {
    constexpr int BN = 128, WN = 32;
    constexpr int WARPS_N = BN / WN;          // 4
    constexpr int MT = WM / 16;
    constexpr int NT = WN / 8;                // 4
    constexpr int RR = R * R;
    constexpr int ROWS = (R == 3) ? 4 : 2;
    constexpr int RS = 72;                    // row stride (floats)
    constexpr int CS = ROWS * RS + 8;         // ch stride: 296 (R3) / 152 (R1)
    constexpr int NG = CIN / 16;
    constexpr int CSPLIT = SPLIT ? CIN / 2 : CIN;
    constexpr int CIN0 = SPLIT ? CIN / 2 : CIN;

    const int tid = threadIdx.x;
    const int lane = tid & 31;
    const int w = tid >> 5;
    const int wm = w / WARPS_N;
    const int wn = w % WARPS_N;

    const int m0 = blockIdx.y * BM;
    const int n0 = blockIdx.x * BN;
    const int b = n0 >> 12;
    const int p0 = n0 & 4095;
    const int y0 = p0 >> 6;

    __shared__ __align__(16) float xwin[16 * CS];
    __shared__ __align__(16) uint32_t Abuf[2][BM * 16];
    const uint32_t win_sm = (uint32_t)__cvta_generic_to_shared(xwin);
    const uint32_t ab_sm0 = (uint32_t)__cvta_generic_to_shared(Abuf[0]);
    const uint32_t ab_sm1 = (uint32_t)__cvta_generic_to_shared(Abuf[1]);

    // zero the pad columns once (cols 0..3 and 68..71 of each (ch,row))
    if (tid < 16 * ROWS) {
        int ch = tid / ROWS, row = tid % ROWS;
        float* p = xwin + ch * CS + row * RS;
        *(float4*)(p) = make_float4(0.f, 0.f, 0.f, 0.f);
        *(float4*)(p + 68) = make_float4(0.f, 0.f, 0.f, 0.f);
    }

    float c[MT][NT][4];
    #pragma unroll
    for (int i = 0; i < MT; i++)
        #pragma unroll
        for (int j = 0; j < NT; j++)
            #pragma unroll
            for (int q = 0; q < 4; q++) c[i][j][q] = 0.0f;

    for (int cg = 0; cg < NG; cg++) {
        // ---- window fill: 16ch x ROWS x 64 cols, aligned cp.async ----
        #pragma unroll
        for (int it = 0; it < (16 * ROWS * 16) / 256; it++) {
            int i = tid + it * 256;
            int f4 = i & 15;
            int row = (i >> 4) & (ROWS - 1);
            int ch = i >> ((R == 3) ? 6 : 5);
            int chg = cg * 16 + ch;
            const float* bp;
            if (SPLIT && chg >= CSPLIT)
                bp = in1 + (((size_t)(b * (CIN - CSPLIT) + chg - CSPLIT)) << 12);
            else
                bp = in0 + (((size_t)(b * CIN0 + chg)) << 12);
            int sy = y0 + row - ((R == 3) ? 1 : 0);
            uint32_t sz = ((unsigned)sy < 64u) ? 16u : 0u;
            cp_async16z(win_sm + (ch * CS + row * RS + 4 + f4 * 4) * 4,
                        bp + (sy << 6) + f4 * 4, sz);
        }
        // ---- A tile for tap 0 ----
        {
            const uint32_t* asrc = wtf + ((size_t)(cg * RR) * (Cout >> 4) + (m0 >> 4)) * 256;
            #pragma unroll
            for (int it = 0; it < BM / 64; it++) {
                int i4 = tid + it * 256;
                cp_async16(ab_sm0 + i4 * 16, asrc + i4 * 4);
            }
        }
        cp_async_commit();

        #pragma unroll
        for (int r = 0; r < RR; r++) {
            if (r + 1 < RR) {
                const uint32_t* asrc =
                    wtf + ((size_t)(cg * RR + r + 1) * (Cout >> 4) + (m0 >> 4)) * 256;
                uint32_t dst = ((r + 1) & 1) ? ab_sm1 : ab_sm0;
                #pragma unroll
                for (int it = 0; it < BM / 64; it++) {
                    int i4 = tid + it * 256;
                    cp_async16(dst + i4 * 16, asrc + i4 * 4);
                }
                cp_async_commit();
                cp_async_wait<1>();
            } else {
                cp_async_wait<0>();
            }
            __syncthreads();

            const int ROWOFF = (R == 3) ? (r / 3) : 0;
            const int COLOFF = (R == 3) ? (r % 3) + 3 : 4;
            const int baseB = (lane & 3) * CS + ((wn >> 1) + ROWOFF) * RS +
                              (wn & 1) * 32 + (lane >> 2) + COLOFF;
            const uint32_t* Ab = Abuf[r & 1];

            #pragma unroll
            for (int ks = 0; ks < 2; ks++) {
                uint32_t af[MT][4];
                uint32_t bf[NT][2];
                #pragma unroll
                for (int mt = 0; mt < MT; mt++) {
                    uint4 t4 = ((const uint4*)Ab)[((wm * MT + mt) * 2 + ks) * 32 + lane];
                    af[mt][0] = t4.x; af[mt][1] = t4.y; af[mt][2] = t4.z; af[mt][3] = t4.w;
                }
                const int bb = baseB + ks * 8 * CS;
                #pragma unroll
                for (int nt = 0; nt < NT; nt++) {
                    bf[nt][0] = __float_as_uint(xwin[bb + nt * 8]);
                    bf[nt][1] = __float_as_uint(xwin[bb + 4 * CS + nt * 8]);
                }
                #pragma unroll
                for (int mt = 0; mt < MT; mt++)
                    #pragma unroll
                    for (int nt = 0; nt < NT; nt++)
                        mma_tf32(c[mt][nt], af[mt], bf[nt]);
            }
            __syncthreads();
        }
    }

    // ---- epilogue ----
    const int g = lane >> 2, t = lane & 3;
    #pragma unroll
    for (int mt = 0; mt < MT; mt++) {
        int row0 = m0 + wm * WM + mt * 16 + g;
        float bs0 = bias[row0];
        float bs1 = bias[row0 + 8];
        #pragma unroll
        for (int nt = 0; nt < NT; nt++) {
            int p = p0 + wn * WN + nt * 8 + t * 2;
            float2 o0, o1;
            o0.x = apply_act<ACT>(c[mt][nt][0] + bs0);
            o0.y = apply_act<ACT>(c[mt][nt][1] + bs0);
            o1.x = apply_act<ACT>(c[mt][nt][2] + bs1);
            o1.y = apply_act<ACT>(c[mt][nt][3] + bs1);
            *(float2*)&out[(((size_t)(b * Cout + row0)) << 12) + p] = o0;
            *(float2*)&out[(((size_t)(b * Cout + row0 + 8)) << 12) + p] = o1;
        }
    }
}

// ------------- generic conv (R4 path) — used only for edge conv -------------
template<int BM, int BN, int WM, int WN, int R, int CIN, int LOG2CIN,
         bool SPLIT, int ACT>
__global__ void __launch_bounds__(256)
conv_mma(const float* __restrict__ in0, const float* __restrict__ in1,
         const uint32_t* __restrict__ wtf, const float* __restrict__ bias,
         float* __restrict__ out, int Cout) {
    constexpr int BK = 16;
    constexpr int WARPS_N = BN / WN;
    constexpr int MT = WM / 16;
    constexpr int NT = WN / 8;
    constexpr int RRtot = R * R;
    constexpr int Ktot = CIN * RRtot;
    constexpr int KtotPad = (Ktot + 15) & ~15;
    constexpr int CSPLIT = SPLIT ? CIN / 2 : CIN;

    const int tid = threadIdx.x;
    const int lane = tid & 31;
    const int w = tid >> 5;
    const int wm = w / WARPS_N;
    const int wn = w % WARPS_N;

    const int m0 = blockIdx.y * BM;
    const int n0 = blockIdx.x * BN;
    const int b = n0 >> 12;
    const int p0 = n0 & 4095;
    const int y0 = p0 >> 6;

    __shared__ __align__(16) uint32_t As[BM * BK];
    __shared__ __align__(16) uint32_t Bs[BN * BK];
    const uint32_t As_sm = (uint32_t)__cvta_generic_to_shared(As);

    float c[MT][NT][4];
    #pragma unroll
    for (int i = 0; i < MT; i++)
        #pragma unroll
        for (int j = 0; j < NT; j++)
            #pragma unroll
            for (int q = 0; q < 4; q++) c[i][j][q] = 0.0f;

    for (int kt = 0; kt < KtotPad / BK; kt++) {
        const int k0 = kt * BK;
        {
            const uint32_t* src = wtf + (kt * (Cout >> 4) + (m0 >> 4)) * 256;
            #pragma unroll
            for (int it = 0; it < (BM * BK) / (256 * 4); it++) {
                int i4 = tid + it * 256;
                cp_async16(As_sm + i4 * 16, src + i4 * 4);
            }
        }
        #pragma unroll
        for (int it = 0; it < (BN * BK) / 256; it++) {
            int i = tid + it * 256;
            int n = i & (BN - 1);
            int k = i / BN;
            int kk = k0 + k;
            int r = kk >> LOG2CIN;
            int ci = kk & (CIN - 1);
            float v = 0.0f;
            {
                int ky = (r * 11) >> 5;
                int kx = r - ky * 3;
                int sy = y0 + (n >> 6) + ky - 1;
                int sx = (n & 63) + kx - 1;
                bool ok = (r < RRtot) & ((unsigned)sy < 64u) & ((unsigned)sx < 64u);
                if (ok) {
                    const float* base;
                    if (SPLIT && ci >= CSPLIT)
                        base = in1 + (((size_t)(b * (CIN - CSPLIT) + (ci - CSPLIT))) << 12);
                    else
                        base = in0 + (((size_t)(b * CSPLIT + ci)) << 12);
                    v = base[(sy << 6) + sx];
                }
            }
            int nt = n >> 3, gg = n & 7;
            int t = k & 3, j = (k >> 2) & 1, ks = k >> 3;
            Bs[(((nt * 2 + ks) * 32) + gg * 4 + t) * 2 + j] = f2tf32(v);
        }
        cp_async_commit();
        cp_async_wait<0>();
        __syncthreads();

        #pragma unroll
        for (int ks = 0; ks < 2; ks++) {
            uint32_t af[MT][4];
            uint32_t bf[NT][2];
            #pragma unroll
            for (int mt = 0; mt < MT; mt++) {
                uint4 t4 = ((const uint4*)As)[((wm * MT + mt) * 2 + ks) * 32 + lane];
                af[mt][0] = t4.x; af[mt][1] = t4.y; af[mt][2] = t4.z; af[mt][3] = t4.w;
            }
            #pragma unroll
            for (int nt = 0; nt < NT; nt++) {
                uint2 t2 = ((const uint2*)Bs)[((wn * NT + nt) * 2 + ks) * 32 + lane];
                bf[nt][0] = t2.x; bf[nt][1] = t2.y;
            }
            #pragma unroll
            for (int mt = 0; mt < MT; mt++)
                #pragma unroll
                for (int nt = 0; nt < NT; nt++)
                    mma_tf32(c[mt][nt], af[mt], bf[nt]);
        }
        __syncthreads();
    }

    const int g = lane >> 2, t = lane & 3;
    #pragma unroll
    for (int mt = 0; mt < MT; mt++) {
        int row0 = m0 + wm * WM + mt * 16 + g;
        float bs0 = bias[row0];
        float bs1 = bias[row0 + 8];
        #pragma unroll
        for (int nt = 0; nt < NT; nt++) {
            int p = p0 + wn * WN + nt * 8 + t * 2;
            float2 o0, o1;
            o0.x = apply_act<ACT>(c[mt][nt][0] + bs0);
            o0.y = apply_act<ACT>(c[mt][nt][1] + bs0);
            o1.x = apply_act<ACT>(c[mt][nt][2] + bs1);
            o1.y = apply_act<ACT>(c[mt][nt][3] + bs1);
            *(float2*)&out[(((size_t)(b * Cout + row0)) << 12) + p] = o0;
            *(float2*)&out[(((size_t)(b * Cout + row0 + 8)) << 12) + p] = o1;
        }
    }
}

// ------------------------ small 1x1 conv (Cout tiny) -------------------------
template<int COUT, int CIN, int ACT>
__global__ void conv1x1_small(const float* __restrict__ in, const float* __restrict__ w,
                              const float* __restrict__ bias, float* __restrict__ out) {
    __shared__ float ws[COUT * CIN];
    for (int i = threadIdx.x; i < COUT * CIN; i += blockDim.x) ws[i] = w[i];
    __syncthreads();
    int idx = blockIdx.x * blockDim.x + threadIdx.x;
    if (idx >= BATCH * HW) return;
    int b = idx >> 12, p = idx & 4095;
    float acc[COUT];
    #pragma unroll
    for (int co = 0; co < COUT; co++) acc[co] = bias[co];
    for (int ci = 0; ci < CIN; ci++) {
        float v = in[((b * CIN + ci) << 12) + p];
        #pragma unroll
        for (int co = 0; co < COUT; co++) acc[co] += ws[co * CIN + ci] * v;
    }
    #pragma unroll
    for (int co = 0; co < COUT; co++)
        out[((b * COUT + co) << 12) + p] = apply_act<ACT>(acc[co]);
}

// ---------------------- GroupNorm(8 groups of 8ch) + GELU -------------------
__global__ void groupnorm_gelu(float* __restrict__ e, const float* __restrict__ g,
                               const float* __restrict__ bta) {
    __shared__ float sh[8];
    int b = blockIdx.x >> 3, grp = blockIdx.x & 7;
    const int base = (b * 64 + grp * 8) << 12;
    float s = 0.0f, s2 = 0.0f;
    for (int i = threadIdx.x; i < 8 * HW; i += blockDim.x) {
        float v = e[base + i];
        s += v; s2 += v * v;
    }
    s = block_reduce_sum_256(s, sh);
    s2 = block_reduce_sum_256(s2, sh);
    float mean = s * (1.0f / 32768.0f);
    float var = s2 * (1.0f / 32768.0f) - mean * mean;
    float rstd = rsqrtf(var + 1e-5f);
    for (int i = threadIdx.x; i < 8 * HW; i += blockDim.x) {
        int ch = grp * 8 + (i >> 12);
        float v = (e[base + i] - mean) * rstd * g[ch] + bta[ch];
        e[base + i] = gelu_exact(v);
    }
}

// ---------------------- attention: S = Q^T K / 8 + edge ---------------------
__global__ void __launch_bounds__(256) qk_kernel(const float* __restrict__ qkv,
                                                 const float* __restrict__ edge,
                                                 float* __restrict__ S) {
    int blk = blockIdx.x;           // b*512 + h*64 + i
    int b = blk >> 9;
    int hi = blk & 511;
    const float* Q = qkv + (((size_t)(b * 1536 + hi)) << 12);
    const float* K = qkv + (((size_t)(b * 1536 + 512 + hi)) << 12);
    const float* E = edge + ((size_t)blk << 6);

    __shared__ float Qs[64 * 64];
    __shared__ float Ks[64 * 64];
    __shared__ float Es[64];
    int tid = threadIdx.x;
    #pragma unroll
    for (int it = 0; it < 4; it++) {
        int i = tid + it * 256;
        ((float4*)Qs)[i] = ((const float4*)Q)[i];
        ((float4*)Ks)[i] = ((const float4*)K)[i];
    }
    if (tid < 64) Es[tid] = E[tid];
    __syncthreads();

    int tW = tid & 15, tw = tid >> 4;
    float acc[4][4];
    #pragma unroll
    for (int r = 0; r < 4; r++)
        #pragma unroll
        for (int c = 0; c < 4; c++) acc[r][c] = 0.0f;

    #pragma unroll 4
    for (int d = 0; d < 64; d++) {
        float4 qv = *(const float4*)&Qs[d * 64 + tw * 4];
        float4 kv = *(const float4*)&Ks[d * 64 + tW * 4];
        float qa[4] = {qv.x, qv.y, qv.z, qv.w};
        float ka[4] = {kv.x, kv.y, kv.z, kv.w};
        #pragma unroll
        for (int r = 0; r < 4; r++)
            #pragma unroll
            for (int c = 0; c < 4; c++) acc[r][c] += qa[r] * ka[c];
    }
    float* So = S + ((size_t)blk << 12);
    #pragma unroll
    for (int r = 0; r < 4; r++) {
        int ww = tw * 4 + r;
        float e = Es[ww];
        #pragma unroll
        for (int c = 0; c < 4; c++)
            So[ww * 64 + tW * 4 + c] = acc[r][c] * 0.125f + e;
    }
}

// ------------------- softmax over i (stride 4096 within bh) -----------------
__global__ void __launch_bounds__(256) softmax_i(float* __restrict__ S) {
    int col = blockIdx.x * blockDim.x + threadIdx.x;
    if (col >= 64 * HW) return;
    int bh = col >> 12, p = col & 4095;
    float* base = S + ((size_t)bh << 18) + p;
    float vals[64];
    float mx = -3.0e38f;
    #pragma unroll
    for (int i = 0; i < 64; i++) {
        vals[i] = base[i << 12];
        mx = fmaxf(mx, vals[i]);
    }
    float sum = 0.0f;
    #pragma unroll
    for (int i = 0; i < 64; i++) {
        vals[i] = expf(vals[i] - mx);
        sum += vals[i];
    }
    float inv = 1.0f / sum;
    #pragma unroll
    for (int i = 0; i < 64; i++) base[i << 12] = vals[i] * inv;
}

// ---------------- agg = V A^T, write into g_agg -----------------------------
__global__ void __launch_bounds__(256) av_kernel(const float* __restrict__ S,
                                                 const float* __restrict__ qkv,
                                                 float* __restrict__ agg) {
    int blk = blockIdx.x; // b*512 + hi
    int b = blk >> 9;
    int hi = blk & 511;
    const float* A = S + ((size_t)blk << 12);
    const float* V = qkv + (((size_t)(b * 1536 + 1024 + hi)) << 12);

    __shared__ float As_[64][65];
    __shared__ float Vs[64][65];
    int tid = threadIdx.x;
    #pragma unroll
    for (int it = 0; it < 16; it++) {
        int i = tid + it * 256;
        int r = i >> 6, cc = i & 63;
        As_[r][cc] = A[i];
        Vs[r][cc] = V[i];
    }
    __syncthreads();

    int tw = tid & 15, td = tid >> 4;
    float acc[4][4];
    #pragma unroll
    for (int r = 0; r < 4; r++)
        #pragma unroll
        for (int cc = 0; cc < 4; cc++) acc[r][cc] = 0.0f;

    #pragma unroll 4
    for (int W = 0; W < 64; W++) {
        float v[4], a[4];
        #pragma unroll
        for (int r = 0; r < 4; r++) v[r] = Vs[td * 4 + r][W];
        #pragma unroll
        for (int cc = 0; cc < 4; cc++) a[cc] = As_[tw * 4 + cc][W];
        #pragma unroll
        for (int r = 0; r < 4; r++)
            #pragma unroll
            for (int cc = 0; cc < 4; cc++) acc[r][cc] += v[r] * a[cc];
    }
    float* outp = agg + (((size_t)(b * 512 + hi)) << 12);
    #pragma unroll
    for (int r = 0; r < 4; r++)
        #pragma unroll
        for (int cc = 0; cc < 4; cc++)
            outp[(td * 4 + r) * 64 + tw * 4 + cc] = acc[r][cc];
}

// ------------------------- BatchNorm stats + SiLU ---------------------------
__global__ void bn_stats(const float* __restrict__ y, float* __restrict__ mean,
                         float* __restrict__ var) {
    __shared__ float sh[8];
    int c = blockIdx.x;
    float s = 0.0f, s2 = 0.0f;
    for (int i = threadIdx.x; i < BATCH * HW; i += blockDim.x) {
        int b = i >> 12, p = i & 4095;
        float v = y[(((size_t)(b * 512 + c)) << 12) + p];
        s += v; s2 += v * v;
    }
    s = block_reduce_sum_256(s, sh);
    s2 = block_reduce_sum_256(s2, sh);
    if (threadIdx.x == 0) {
        float m = s * (1.0f / 32768.0f);
        mean[c] = m;
        var[c] = s2 * (1.0f / 32768.0f) - m * m;
    }
}

__global__ void bn_silu(const float* __restrict__ y, const float* __restrict__ mean,
                        const float* __restrict__ var, const float* __restrict__ g,
                        const float* __restrict__ bta, float* __restrict__ out) {
    int idx = blockIdx.x * blockDim.x + threadIdx.x;
    int c = (idx >> 12) & 511;
    float v = (y[idx] - mean[c]) * rsqrtf(var[c] + 1e-5f) * g[c] + bta[c];
    out[idx] = v * sigmoidf_(v);
}

// ------------------------------- launcher -----------------------------------
static void* sym_addr(const void* symbol) {
    void* p = nullptr;
    cudaGetSymbolAddress(&p, symbol);
    return p;
}

extern "C" void kernel_launch(void* const* d_in, const int* in_sizes, int n_in,
                              void* d_out, int out_size) {
    const float* x       = (const float*)d_in[0];
    const float* box_w1  = (const float*)d_in[1];
    const float* box_b1  = (const float*)d_in[2];
    const float* box_w2  = (const float*)d_in[3];
    const float* box_b2  = (const float*)d_in[4];
    const float* edge_w1 = (const float*)d_in[5];
    const float* edge_b1 = (const float*)d_in[6];
    const float* gn_g    = (const float*)d_in[7];
    const float* gn_b    = (const float*)d_in[8];
    const float* edge_w2 = (const float*)d_in[9];
    const float* edge_b2 = (const float*)d_in[10];
    const float* qkv_w   = (const float*)d_in[11];
    const float* qkv_b   = (const float*)d_in[12];
    const float* fus_w   = (const float*)d_in[13];
    const float* fus_b   = (const float*)d_in[14];
    const float* bn_g    = (const float*)d_in[15];
    const float* bn_b    = (const float*)d_in[16];
    float* out = (float*)d_out;

    uint32_t* wtf_box1  = (uint32_t*)sym_addr(g_wtf_box1);
    uint32_t* wtf_edge1 = (uint32_t*)sym_addr(g_wtf_edge1);
    uint32_t* wtf_qkv   = (uint32_t*)sym_addr(g_wtf_qkv);
    uint32_t* wtf_fus   = (uint32_t*)sym_addr(g_wtf_fus);
    float* t1       = (float*)sym_addr(g_t1);
    float* boxes    = (float*)sym_addr(g_boxes);
    float* e1       = (float*)sym_addr(g_e1);
    float* edge     = (float*)sym_addr(g_edge);
    float* qkvbuf   = (float*)sym_addr(g_qkv);
    float* Sbuf     = (float*)sym_addr(g_S);
    float* aggbuf   = (float*)sym_addr(g_agg);
    float* ybuf     = (float*)sym_addr(g_y);
    float* bnmean   = (float*)sym_addr(g_bnmean);
    float* bnvar    = (float*)sym_addr(g_bnvar);

    // weight prep
    prep_wg<<<(64 * 4608 + 255) / 256, 256>>>(box_w1, wtf_box1, 64, 512, 9);
    prep_w<<<(64 * 48 + 255) / 256, 256>>>(edge_w1, wtf_edge1, 64, 4, 9, 2, 48);
    prep_wg<<<(1536 * 512 + 255) / 256, 256>>>(qkv_w, wtf_qkv, 1536, 512, 1);
    prep_wg<<<(512 * 9216 + 255) / 256, 256>>>(fus_w, wtf_fus, 512, 1024, 9);

    // box_net: conv3x3(512->64)+GELU -> conv1x1(64->4)+sigmoid
    conv_win<64, 32, 3, 512, false, 1><<<dim3(256, 1), 256>>>(
        x, x, wtf_box1, box_b1, t1, 64);
    conv1x1_small<4, 64, 2><<<128, 256>>>(t1, box_w2, box_b2, boxes);

    // edge_net: conv3x3(4->64) -> GN+GELU -> conv1x1(64->8)
    conv_mma<64, 128, 32, 32, 3, 4, 2, false, 0><<<dim3(256, 1), 256>>>(
        boxes, boxes, wtf_edge1, edge_b1, e1, 64);
    groupnorm_gelu<<<64, 256>>>(e1, gn_g, gn_b);
    conv1x1_small<8, 64, 0><<<128, 256>>>(e1, edge_w2, edge_b2, edge);

    // qkv 1x1 conv (512 -> 1536)
    conv_win<128, 64, 1, 512, false, 0><<<dim3(256, 12), 256>>>(
        x, x, wtf_qkv, qkv_b, qkvbuf, 1536);

    // attention
    qk_kernel<<<4096, 256>>>(qkvbuf, edge, Sbuf);
    softmax_i<<<1024, 256>>>(Sbuf);
    av_kernel<<<4096, 256>>>(Sbuf, qkvbuf, aggbuf);

    // fusion conv3x3 (x | agg : 1024 -> 512) + BN + SiLU
    conv_win<128, 64, 3, 1024, true, 0><<<dim3(256, 4), 256>>>(
        x, aggbuf, wtf_fus, fus_b, ybuf, 512);
    bn_stats<<<512, 256>>>(ybuf, bnmean, bnvar);
    bn_silu<<<65536, 256>>>(ybuf, bnmean, bnvar, bn_g, bn_b, out);
}